// round 7
// baseline (speedup 1.0000x reference)
#include <cuda_runtime.h>
#include <math.h>

#define BATCH    16384
#define MAZE_LEN 3844
#define NWARPS   8192          // each warp does rows w and w+8192
#define GRID     2048          // 128-thread CTAs, 4 warps each

// 120 needed columns per row (3721 double-counted), all reciprocal-summed:
//   -log(clip(prod, e^-90)) == min(log(S - 127), 90)
// (S includes 8 dummy 1.0-reciprocals from inactive mid lanes per row.)
//
// Load layout per row (all 4B scalar loads, ~37 distinct 128B lines = minimum):
//   head: lane l -> idx {1, 6, 4l+1}
//   tail: lane l -> idx {3717+4l, 3721, 3839, 3841}
//   mid:  2 instructions; lanes (2k,2k+1) load BOTH values of pair p
//         from the SAME 128B line.
//
// Single-node graph: no memset. Blocks atomicAdd into g_acc; the last block
// writes d_out and resets {g_acc, g_cnt} to zero so every replay starts clean.

__device__ float    g_acc;     // zero-initialized at module load, self-resetting
__device__ unsigned g_cnt;

__device__ __forceinline__ float fast_rcp(float x) {
    float r;
    asm("rcp.approx.ftz.f32 %0, %1;" : "=f"(r) : "f"(x));
    return r;
}

// Fold 4 reciprocals into one MUFU.RCP.
__device__ __forceinline__ float fold4(float h, float t, float m0, float m1) {
    const float a   = h * t;
    const float b   = m0 * m1;
    const float num = (h + t) * b + (m0 + m1) * a;
    return num * fast_rcp(a * b);
}

__global__ __launch_bounds__(128)
void fuzzy_chain_kernel(const float* __restrict__ maze, float* __restrict__ out)
{
    const int warp_local  = threadIdx.x >> 5;                 // 0..3
    const int warp_global = blockIdx.x * 4 + warp_local;
    const int lane        = threadIdx.x & 31;

    // ---- per-lane scalar indices (shared by both rows) -------------------
    int h_i = 4 * lane + 1;
    if (lane == 0) h_i = 1;
    if (lane == 1) h_i = 6;

    int t_i = 3717 + 4 * lane;
    if (lane == 29) t_i = 3721;                   // duplicate 3721
    if (lane == 30) t_i = 3839;
    if (lane == 31) t_i = 3841;

    const int k     = lane >> 1;
    const int comp  = lane & 1;
    const int p1    = 16 + k;
    const bool act1 = (p1 < 28);
    const int m0_i  = 124 * k + 245 + 4 * comp;
    const int m1_i  = 124 * (act1 ? p1 : 27) + 245 + 4 * comp;

    const float* __restrict__ row0 = maze + (size_t)warp_global * MAZE_LEN;
    const float* __restrict__ row1 = maze + (size_t)(warp_global + NWARPS) * MAZE_LEN;

    // ---- front-batch all 8 scalar loads ----------------------------------
    const float h0  = __ldg(row0 + h_i);
    const float t0  = __ldg(row0 + t_i);
    const float a0  = __ldg(row0 + m0_i);
    const float b0l = __ldg(row0 + m1_i);
    const float h1  = __ldg(row1 + h_i);
    const float t1  = __ldg(row1 + t_i);
    const float a1  = __ldg(row1 + m0_i);
    const float b1l = __ldg(row1 + m1_i);

    const float b0 = act1 ? b0l : 1.0f;           // dummy -> rcp(1)=1, in constant
    const float b1 = act1 ? b1l : 1.0f;

    float s0 = fold4(h0, t0, a0, b0);
    float s1 = fold4(h1, t1, a1, b1);

    // ---- warp reduction of both rows' S ----------------------------------
    #pragma unroll
    for (int off = 16; off > 0; off >>= 1) {
        s0 += __shfl_xor_sync(0xffffffffu, s0, off);
        s1 += __shfl_xor_sync(0xffffffffu, s1, off);
    }

    __shared__ float warp_vals[4];
    if (lane == 0) {
        // x==0 -> inf -> fminf -> 90; two zeros -> NaN -> fminf -> 90 (matches clip).
        const float v0 = fminf(logf(s0 - 127.0f), 90.0f);
        const float v1 = fminf(logf(s1 - 127.0f), 90.0f);
        warp_vals[warp_local] = v0 + v1;
    }
    __syncthreads();

    if (threadIdx.x == 0) {
        const float t = warp_vals[0] + warp_vals[1] + warp_vals[2] + warp_vals[3];
        atomicAdd(&g_acc, t);
        __threadfence();
        const unsigned old = atomicAdd(&g_cnt, 1u);
        if (old == GRID - 1u) {
            // All partials visible (their g_acc adds precede their g_cnt adds).
            const float total = atomicAdd(&g_acc, 0.0f);
            out[0] = total * (1.0f / (float)BATCH);   // exact power-of-two scale
            g_acc = 0.0f;                             // restore for next replay
            g_cnt = 0u;
        }
    }
}

extern "C" void kernel_launch(void* const* d_in, const int* in_sizes, int n_in,
                              void* d_out, int out_size)
{
    const float* maze = (const float*)d_in[0];
    float*       out  = (float*)d_out;
    fuzzy_chain_kernel<<<GRID, 128>>>(maze, out);
}

// round 8
// speedup vs baseline: 1.0918x; 1.0918x over previous
#include <cuda_runtime.h>
#include <math.h>

#define BATCH    16384
#define MAZE_LEN 3844
#define NWARPS   4096          // each warp does rows w, w+4096, w+8192, w+12288

// 120 needed columns per row (3721 double-counted), all reciprocal-summed:
//   -log(clip(prod, e^-90)) == min(log(S - 127), 90)
// (S includes 8 dummy 1.0-reciprocals from inactive mid lanes per row.)
//
// Load layout per row (all 4B scalar loads, ~37 distinct 128B lines = minimum):
//   head: lane l -> idx {1, 6, 4l+1}
//   tail: lane l -> idx {3717+4l, 3721, 3839, 3841}
//   mid:  2 instructions; lanes (2k,2k+1) load BOTH values of pair p
//         from the SAME 128B line.
// 4 rows/warp -> 16 front-batched loads/lane for latency hiding (warm L2 hits).

__device__ __forceinline__ float fast_rcp(float x) {
    float r;
    asm("rcp.approx.ftz.f32 %0, %1;" : "=f"(r) : "f"(x));
    return r;
}

// Fold 4 reciprocals into one MUFU.RCP.
__device__ __forceinline__ float fold4(float h, float t, float m0, float m1) {
    const float a   = h * t;
    const float b   = m0 * m1;
    const float num = (h + t) * b + (m0 + m1) * a;
    return num * fast_rcp(a * b);
}

__global__ __launch_bounds__(256)
void fuzzy_chain_kernel(const float* __restrict__ maze, float* __restrict__ out)
{
    const int warp_local  = threadIdx.x >> 5;                 // 0..7
    const int warp_global = blockIdx.x * 8 + warp_local;
    const int lane        = threadIdx.x & 31;

    // ---- per-lane scalar indices (shared by all 4 rows) ------------------
    int h_i = 4 * lane + 1;
    if (lane == 0) h_i = 1;
    if (lane == 1) h_i = 6;

    int t_i = 3717 + 4 * lane;
    if (lane == 29) t_i = 3721;                   // duplicate 3721
    if (lane == 30) t_i = 3839;
    if (lane == 31) t_i = 3841;

    const int k     = lane >> 1;
    const int comp  = lane & 1;
    const int p1    = 16 + k;
    const bool act1 = (p1 < 28);
    const int m0_i  = 124 * k + 245 + 4 * comp;
    const int m1_i  = 124 * (act1 ? p1 : 27) + 245 + 4 * comp;

    const float* __restrict__ r0 = maze + (size_t)warp_global * MAZE_LEN;
    const float* __restrict__ r1 = r0 + (size_t)NWARPS * MAZE_LEN;
    const float* __restrict__ r2 = r1 + (size_t)NWARPS * MAZE_LEN;
    const float* __restrict__ r3 = r2 + (size_t)NWARPS * MAZE_LEN;

    // ---- front-batch all 16 scalar loads (MLP=16) ------------------------
    const float h0 = __ldg(r0 + h_i), t0 = __ldg(r0 + t_i);
    const float a0 = __ldg(r0 + m0_i), b0l = __ldg(r0 + m1_i);
    const float h1 = __ldg(r1 + h_i), t1 = __ldg(r1 + t_i);
    const float a1 = __ldg(r1 + m0_i), b1l = __ldg(r1 + m1_i);
    const float h2 = __ldg(r2 + h_i), t2 = __ldg(r2 + t_i);
    const float a2 = __ldg(r2 + m0_i), b2l = __ldg(r2 + m1_i);
    const float h3 = __ldg(r3 + h_i), t3 = __ldg(r3 + t_i);
    const float a3 = __ldg(r3 + m0_i), b3l = __ldg(r3 + m1_i);

    const float b0 = act1 ? b0l : 1.0f;           // dummy -> rcp(1)=1, in constant
    const float b1 = act1 ? b1l : 1.0f;
    const float b2 = act1 ? b2l : 1.0f;
    const float b3 = act1 ? b3l : 1.0f;

    float s0 = fold4(h0, t0, a0, b0);
    float s1 = fold4(h1, t1, a1, b1);
    float s2 = fold4(h2, t2, a2, b2);
    float s3 = fold4(h3, t3, a3, b3);

    // ---- warp reduction of all 4 rows' S ---------------------------------
    #pragma unroll
    for (int off = 16; off > 0; off >>= 1) {
        s0 += __shfl_xor_sync(0xffffffffu, s0, off);
        s1 += __shfl_xor_sync(0xffffffffu, s1, off);
        s2 += __shfl_xor_sync(0xffffffffu, s2, off);
        s3 += __shfl_xor_sync(0xffffffffu, s3, off);
    }

    __shared__ float warp_vals[8];
    if (lane == 0) {
        // x==0 -> inf -> fminf -> 90; two zeros -> NaN -> fminf -> 90 (matches clip).
        const float v0 = fminf(logf(s0 - 127.0f), 90.0f);
        const float v1 = fminf(logf(s1 - 127.0f), 90.0f);
        const float v2 = fminf(logf(s2 - 127.0f), 90.0f);
        const float v3 = fminf(logf(s3 - 127.0f), 90.0f);
        warp_vals[warp_local] = (v0 + v1) + (v2 + v3);
    }
    __syncthreads();

    if (threadIdx.x == 0) {
        float t = 0.0f;
        #pragma unroll
        for (int i = 0; i < 8; i++) t += warp_vals[i];
        atomicAdd(out, t * (1.0f / (float)BATCH));   // exact power-of-two scale
    }
}

extern "C" void kernel_launch(void* const* d_in, const int* in_sizes, int n_in,
                              void* d_out, int out_size)
{
    const float* maze = (const float*)d_in[0];
    float*       out  = (float*)d_out;

    cudaMemsetAsync(out, 0, sizeof(float), 0);

    const int blocks = NWARPS / 8;                  // 512 CTAs, 256 threads each
    fuzzy_chain_kernel<<<blocks, 256>>>(maze, out);
}